// round 6
// baseline (speedup 1.0000x reference)
#include <cuda_runtime.h>

// ---------------------------------------------------------------------------
// FanoCoupling: out = x + scatter-add over 7 Fano lines of softmax-gated
// Linear(concat(x_i, x_j)).
//
// Reduction: W = [W1 | W2], each 64x64.  Only 8 unique half-matvecs needed:
//   A0=W1 x0, A1=W1 x1, A3=W1 x3, A4=W1 x4, B1=W2 x1, B2=W2 x2, B3=W2 x3, B5=W2 x5
// Combine:
//   out0=x0, out1=x1, out3=x3
//   out2 = x2 + g0*(A0+B1+b)
//   out4 = x4 + g1*(A0+B3+b)
//   out5 = x5 + g3*(A1+B3+b) + g6*(A4+B2+b)
//   out6 = x6 + g2*(A0+B5+b) + g4*(A4+B1+b) + g5*(A3+B2+b)
//
// R5 layout: z-split warps.  Warp w covers z = lane + (w>=4)*32 (ONE z per
// lane) and rows [ (w&3)*4 .. (w&3)*4+3 ) of the 16-row tile; the warp pair
// (w, w^4) covers the same rows.  Per iteration: 2 weight LDS.128 (vs 4 in
// R4), amortized over 4 rows (vs 2) -> 4x less weight crossbar per row.
// Packed fma.rn.f32x2 throughout.
// ---------------------------------------------------------------------------

#define WSTRIDE 68              // floats per weight row in smem (17 x 16B)
#define RPW 4                   // rows per warp
#define ROWS_PER_CTA 16
#define ROW 448                 // floats per batch row (7*64)

__device__ __forceinline__ void fma2(unsigned long long &acc,
                                     unsigned long long a,
                                     unsigned long long b) {
    asm("fma.rn.f32x2 %0, %1, %2, %0;" : "+l"(acc) : "l"(a), "l"(b));
}

__device__ __forceinline__ float accsum(unsigned long long a) {
    float lo = __uint_as_float((unsigned int)(a & 0xffffffffULL));
    float hi = __uint_as_float((unsigned int)(a >> 32));
    return lo + hi;
}

__global__ __launch_bounds__(256, 2)
void fano_kernel(const float* __restrict__ x, const float* __restrict__ W,
                 const float* __restrict__ bias, const float* __restrict__ gates,
                 float* __restrict__ out, int nrows)
{
    extern __shared__ float smem[];
    float* w1s = smem;                        // [64][WSTRIDE]
    float* w2s = w1s + 64 * WSTRIDE;          // [64][WSTRIDE]
    float* xs  = w2s + 64 * WSTRIDE;          // [ROWS_PER_CTA][ROW]

    const int tid = threadIdx.x;

    // --- stage weights: W[z][0:64] -> w1s, W[z][64:128] -> w2s -------------
    for (int i = tid; i < 64 * 128; i += 256) {
        int z = i >> 7, f = i & 127;
        float v = W[i];
        if (f < 64) w1s[z * WSTRIDE + f]        = v;
        else        w2s[z * WSTRIDE + (f - 64)] = v;
    }

    // --- stage x tile (16 rows, float4 coalesced) --------------------------
    long long rowbase  = (long long)blockIdx.x * ROWS_PER_CTA;
    long long elembase = rowbase * ROW;
    int tile_rows = (nrows - rowbase < ROWS_PER_CTA) ? (int)(nrows - rowbase)
                                                     : ROWS_PER_CTA;
    int tile_e4 = tile_rows * (ROW / 4);
    const float4* gx = reinterpret_cast<const float4*>(x + elembase);
    float4* sx = reinterpret_cast<float4*>(xs);
    for (int i = tid; i < tile_e4; i += 256) sx[i] = gx[i];

    __syncthreads();

    const int warp = tid >> 5, lane = tid & 31;
    const int half = warp >> 2;               // 0: z=lane, 1: z=lane+32
    const int rgrp = warp & 3;                // row group within tile
    const int z = lane + half * 32;

    const ulonglong2* w1v = reinterpret_cast<const ulonglong2*>(w1s) + z * (WSTRIDE / 4);
    const ulonglong2* w2v = reinterpret_cast<const ulonglong2*>(w2s) + z * (WSTRIDE / 4);
    const ulonglong2* xv  = reinterpret_cast<const ulonglong2*>(xs)
                          + rgrp * RPW * (ROW / 4);

    // acc[r][res]: res order A0 A1 A3 A4 B1 B2 B3 B5 (one z per lane)
    unsigned long long acc[RPW][8];
    #pragma unroll
    for (int r = 0; r < RPW; r++)
        #pragma unroll
        for (int j = 0; j < 8; j++) acc[r][j] = 0ULL;

    #pragma unroll 4
    for (int it = 0; it < 16; it++) {          // covers f = 4*it .. 4*it+3
        ulonglong2 w1 = w1v[it];               // LDS.128, per-lane distinct z rows
        ulonglong2 w2 = w2v[it];
        #pragma unroll
        for (int r = 0; r < RPW; r++) {
            const ulonglong2* xc = xv + r * (ROW / 4) + it;
            ulonglong2 x0 = xc[0 * 16];        // broadcast LDS.128 (uniform addr)
            ulonglong2 x1 = xc[1 * 16];
            ulonglong2 x2 = xc[2 * 16];
            ulonglong2 x3 = xc[3 * 16];
            ulonglong2 x4 = xc[4 * 16];
            ulonglong2 x5 = xc[5 * 16];
            fma2(acc[r][0], w1.x, x0.x); fma2(acc[r][0], w1.y, x0.y);  // A0
            fma2(acc[r][1], w1.x, x1.x); fma2(acc[r][1], w1.y, x1.y);  // A1
            fma2(acc[r][2], w1.x, x3.x); fma2(acc[r][2], w1.y, x3.y);  // A3
            fma2(acc[r][3], w1.x, x4.x); fma2(acc[r][3], w1.y, x4.y);  // A4
            fma2(acc[r][4], w2.x, x1.x); fma2(acc[r][4], w2.y, x1.y);  // B1
            fma2(acc[r][5], w2.x, x2.x); fma2(acc[r][5], w2.y, x2.y);  // B2
            fma2(acc[r][6], w2.x, x3.x); fma2(acc[r][6], w2.y, x3.y);  // B3
            fma2(acc[r][7], w2.x, x5.x); fma2(acc[r][7], w2.y, x5.y);  // B5
        }
    }

    // --- gates softmax (tiny, per-thread) ----------------------------------
    float graw[7];
    #pragma unroll
    for (int i = 0; i < 7; i++) graw[i] = gates[i];
    float m = graw[0];
    #pragma unroll
    for (int i = 1; i < 7; i++) m = fmaxf(m, graw[i]);
    float g[7], s = 0.f;
    #pragma unroll
    for (int i = 0; i < 7; i++) { g[i] = expf(graw[i] - m); s += g[i]; }
    float inv = 1.f / s;
    #pragma unroll
    for (int i = 0; i < 7; i++) g[i] *= inv;

    const float bz = bias[z];

    // --- epilogue: each warp writes its z-half of its 4 rows ---------------
    #pragma unroll
    for (int r = 0; r < RPW; r++) {
        long long row = rowbase + rgrp * RPW + r;
        if (row >= nrows) break;
        float* orow = out + row * (long long)ROW + z;
        const float* xrow = xs + (rgrp * RPW + r) * ROW + z;

        float a0  = accsum(acc[r][0]);
        float a1  = accsum(acc[r][1]);
        float a3  = accsum(acc[r][2]);
        float a4  = accsum(acc[r][3]);
        float b1v = accsum(acc[r][4]);
        float b2v = accsum(acc[r][5]);
        float b3v = accsum(acc[r][6]);
        float b5v = accsum(acc[r][7]);

        orow[0 * 64] = xrow[0 * 64];
        orow[1 * 64] = xrow[1 * 64];
        orow[2 * 64] = xrow[2 * 64] + g[0] * (a0 + b1v + bz);
        orow[3 * 64] = xrow[3 * 64];
        orow[4 * 64] = xrow[4 * 64] + g[1] * (a0 + b3v + bz);
        orow[5 * 64] = xrow[5 * 64] + g[3] * (a1 + b3v + bz)
                                    + g[6] * (a4 + b2v + bz);
        orow[6 * 64] = xrow[6 * 64] + g[2] * (a0 + b5v + bz)
                                    + g[4] * (a4 + b1v + bz)
                                    + g[5] * (a3 + b2v + bz);
    }
}

extern "C" void kernel_launch(void* const* d_in, const int* in_sizes, int n_in,
                              void* d_out, int out_size) {
    const float* x     = (const float*)d_in[0];   // colony_states [B,7,64]
    const float* W     = (const float*)d_in[1];   // [64,128]
    const float* bias  = (const float*)d_in[2];   // [64]
    const float* gates = (const float*)d_in[3];   // [7]
    float* out = (float*)d_out;

    int nrows = in_sizes[0] / ROW;
    int smem_bytes = (2 * 64 * WSTRIDE + ROWS_PER_CTA * ROW) * (int)sizeof(float);
    cudaFuncSetAttribute(fano_kernel,
                         cudaFuncAttributeMaxDynamicSharedMemorySize, smem_bytes);
    int ctas = (nrows + ROWS_PER_CTA - 1) / ROWS_PER_CTA;
    fano_kernel<<<ctas, 256, smem_bytes>>>(x, W, bias, gates, out, nrows);
}